// round 15
// baseline (speedup 1.0000x reference)
#include <cuda_runtime.h>
#include <mma.h>
#include <cuda_fp16.h>
#include <cstdint>

using namespace nvcuda;

#define B_  8
#define S_  2048
#define E_  2048
#define H_  16
#define D_  128
#define BH_ (B_ * H_)
#define NCHUNK_ 4
#define CHUNK_S_ (S_ / NCHUNK_)   // 512
#define EPS_ 1e-6f
#define DEN_SCALE_ 4096.0f
#define INV_DEN_SCALE_ (1.0f / 4096.0f)

// fp16 fragments
typedef wmma::fragment<wmma::matrix_a, 16, 16, 16, __half, wmma::row_major> AFragH;
typedef wmma::fragment<wmma::matrix_a, 16, 16, 16, __half, wmma::col_major> ATFragH;
typedef wmma::fragment<wmma::matrix_b, 16, 16, 16, __half, wmma::row_major> BFragH;
typedef wmma::fragment<wmma::accumulator, 16, 16, 16, float> CFragH;

__device__ __forceinline__ float phi_(float y) { return (y > 0.f) ? (y + 1.f) : expf(y); }

__device__ __forceinline__ void f4_to_h4(__half* smem, const float4 v) {
    __half2 h0 = __floats2half2_rn(v.x, v.y);
    __half2 h1 = __floats2half2_rn(v.z, v.w);
    uint2 u;
    u.x = *(uint32_t*)&h0;
    u.y = *(uint32_t*)&h1;
    *(uint2*)smem = u;
}

__device__ __forceinline__ void cpasync16(void* smem, const void* gmem) {
    uint32_t s = (uint32_t)__cvta_generic_to_shared(smem);
    asm volatile("cp.async.cg.shared.global [%0], [%1], 16;" :: "r"(s), "l"(gmem));
}
#define CP_COMMIT()  asm volatile("cp.async.commit_group;")
#define CP_WAIT(N)   asm volatile("cp.async.wait_group %0;" :: "n"(N))

// ---------------- scratch (__device__ globals; no allocation allowed) ----------------
__device__ float  g_kvp[(size_t)BH_ * NCHUNK_ * D_ * D_];   // 32 MB
__device__ float  g_ksp[(size_t)BH_ * NCHUNK_ * D_];
__device__ __half g_kvh[(size_t)BH_ * D_ * D_];             // 4 MB fp16 kv
__device__ float  g_ks [(size_t)BH_ * D_];
__device__ __half g_combh[(size_t)B_ * S_ * E_];            // 64 MB fp16 combined heads
__device__ __half g_woh [(size_t)E_ * E_];                  // 8 MB fp16 Wo

// ===========================================================================
// Prep: convert Wo -> fp16. (unchanged)
// ===========================================================================
__global__ void wo_half_kernel(const float4* __restrict__ src) {
    const int n4 = (E_ * E_) / 4;
    int i = blockIdx.x * blockDim.x + threadIdx.x;
    int stride = gridDim.x * blockDim.x;
    for (; i < n4; i += stride) {
        float4 v = src[i];
        __half2* d = (__half2*)&g_woh[(size_t)i * 4];
        d[0] = __floats2half2_rn(v.x, v.y);
        d[1] = __floats2half2_rn(v.z, v.w);
    }
}

// ===========================================================================
// Kernel A: fused K-proj, V-proj, phi, partial kv & ksum — ALL fp16 mma.
// (unchanged from passing round 13)
// ===========================================================================
union KvSmem {
    struct { __half XsH[32][40]; __half WkH[32][136]; __half WvH[32][136]; } p1;
    struct { float StageF[32][132]; __half KtH[32][136]; __half VtH[32][136]; } p2;
};

__global__ void __launch_bounds__(256) fused_kv_kernel(const float* __restrict__ x,
                                                       const float* __restrict__ Wk,
                                                       const float* __restrict__ Wv) {
    __shared__ KvSmem sm;

    const int chunk = blockIdx.x;
    const int bh    = blockIdx.y;
    const int b = bh / H_, h = bh % H_;

    const float* Wkh = Wk + (size_t)h * D_ * D_;
    const float* Wvh = Wv + (size_t)h * D_ * D_;
    const float* Xb  = x + (size_t)b * S_ * E_ + (size_t)h * D_;

    const int tid  = threadIdx.x;
    const int warp = tid >> 5;
    const int lane = tid & 31;
    const int wm1 = warp & 1;
    const int wn1 = warp >> 1;
    const int wm2 = warp & 3;
    const int wn2 = warp >> 2;

    CFragH acc_kv[2][4];
#pragma unroll
    for (int i = 0; i < 2; i++)
#pragma unroll
        for (int j = 0; j < 4; j++) wmma::fill_fragment(acc_kv[i][j], 0.f);

    float ksum_acc = 0.f;

    for (int sub = 0; sub < CHUNK_S_ / 32; sub++) {
        const int s0 = chunk * CHUNK_S_ + sub * 32;

        CFragH acck[2], accv[2];
#pragma unroll
        for (int j = 0; j < 2; j++) { wmma::fill_fragment(acck[j], 0.f); wmma::fill_fragment(accv[j], 0.f); }

        for (int k0 = 0; k0 < D_; k0 += 32) {
            {
                int r = tid >> 3, c4 = (tid & 7) * 4;
                f4_to_h4(&sm.p1.XsH[r][c4], *(const float4*)&Xb[(size_t)(s0 + r) * E_ + k0 + c4]);
            }
#pragma unroll
            for (int t = 0; t < 4; t++) {
                int f4i = tid + t * 256;
                int r = f4i >> 5, c4 = (f4i & 31) * 4;
                f4_to_h4(&sm.p1.WkH[r][c4], *(const float4*)&Wkh[(size_t)(k0 + r) * D_ + c4]);
                f4_to_h4(&sm.p1.WvH[r][c4], *(const float4*)&Wvh[(size_t)(k0 + r) * D_ + c4]);
            }
            __syncthreads();
#pragma unroll
            for (int kk = 0; kk < 2; kk++) {
                AFragH a;
                wmma::load_matrix_sync(a, &sm.p1.XsH[wm1 * 16][kk * 16], 40);
#pragma unroll
                for (int j = 0; j < 2; j++) {
                    BFragH bfr;
                    wmma::load_matrix_sync(bfr, &sm.p1.WkH[kk * 16][wn1 * 32 + j * 16], 136);
                    wmma::mma_sync(acck[j], a, bfr, acck[j]);
                    wmma::load_matrix_sync(bfr, &sm.p1.WvH[kk * 16][wn1 * 32 + j * 16], 136);
                    wmma::mma_sync(accv[j], a, bfr, accv[j]);
                }
            }
            __syncthreads();
        }

#pragma unroll
        for (int j = 0; j < 2; j++) {
#pragma unroll
            for (int e = 0; e < acck[j].num_elements; e++) acck[j].x[e] = phi_(acck[j].x[e]);
            wmma::store_matrix_sync(&sm.p2.StageF[wm1 * 16][wn1 * 32 + j * 16], acck[j], 132, wmma::mem_row_major);
        }
        __syncthreads();
        if (warp < 4) {
            const int col = warp * 32 + lane;
#pragma unroll 8
            for (int r = 0; r < 32; r++) ksum_acc += sm.p2.StageF[r][col];
        }
#pragma unroll
        for (int t = 0; t < 8; t++) {
            int i = tid + t * 256;
            int r = i >> 6, c2 = i & 63;
            *(__half2*)&sm.p2.KtH[r][c2 * 2] =
                __floats2half2_rn(sm.p2.StageF[r][c2 * 2], sm.p2.StageF[r][c2 * 2 + 1]);
        }
        __syncthreads();

#pragma unroll
        for (int j = 0; j < 2; j++)
            wmma::store_matrix_sync(&sm.p2.StageF[wm1 * 16][wn1 * 32 + j * 16], accv[j], 132, wmma::mem_row_major);
        __syncthreads();
#pragma unroll
        for (int t = 0; t < 8; t++) {
            int i = tid + t * 256;
            int r = i >> 6, c2 = i & 63;
            *(__half2*)&sm.p2.VtH[r][c2 * 2] =
                __floats2half2_rn(sm.p2.StageF[r][c2 * 2], sm.p2.StageF[r][c2 * 2 + 1]);
        }
        __syncthreads();

#pragma unroll
        for (int kk = 0; kk < 2; kk++) {
            ATFragH a2[2];
#pragma unroll
            for (int i = 0; i < 2; i++)
                wmma::load_matrix_sync(a2[i], &sm.p2.KtH[kk * 16][wm2 * 32 + i * 16], 136);
#pragma unroll
            for (int j = 0; j < 4; j++) {
                BFragH bfr;
                wmma::load_matrix_sync(bfr, &sm.p2.VtH[kk * 16][wn2 * 64 + j * 16], 136);
#pragma unroll
                for (int i = 0; i < 2; i++) wmma::mma_sync(acc_kv[i][j], a2[i], bfr, acc_kv[i][j]);
            }
        }
        __syncthreads();
    }

    float* kvp = g_kvp + ((size_t)bh * NCHUNK_ + chunk) * D_ * D_;
#pragma unroll
    for (int i = 0; i < 2; i++)
#pragma unroll
        for (int j = 0; j < 4; j++)
            wmma::store_matrix_sync(&kvp[(size_t)(wm2 * 32 + i * 16) * D_ + wn2 * 64 + j * 16],
                                    acc_kv[i][j], D_, wmma::mem_row_major);
    if (warp < 4)
        g_ksp[((size_t)bh * NCHUNK_ + chunk) * D_ + warp * 32 + lane] = ksum_acc;
}

// ===========================================================================
// Kernel A2: reduce the NCHUNK partials; kv -> fp16. (unchanged)
// ===========================================================================
__global__ void reduce_kernel() {
    const int bh = blockIdx.x;
    const int tid = threadIdx.x;
    const float* kvp = g_kvp + (size_t)bh * NCHUNK_ * D_ * D_;
    __half* kv = g_kvh + (size_t)bh * D_ * D_;
    for (int i = tid; i < D_ * D_; i += 256) {
        float s = 0.f;
#pragma unroll
        for (int c = 0; c < NCHUNK_; c++) s += kvp[(size_t)c * D_ * D_ + i];
        kv[i] = __float2half_rn(s);
    }
    if (tid < D_) {
        const float* ksp = g_ksp + (size_t)bh * NCHUNK_ * D_;
        float s = 0.f;
#pragma unroll
        for (int c = 0; c < NCHUNK_; c++) s += ksp[(size_t)c * D_ + tid];
        g_ks[(size_t)bh * D_ + tid] = s;
    }
}

// ===========================================================================
// Kernel B v2: fused Q-proj + phi + ctx, all-fp16, 64-row tiles.
// grid = (S/64, BH), block 256 (8 warps): wm=warp&3 (16-row blocks),
// wn=warp>>2 (64-col blocks). Dynamic smem ~60.7 KB.
// ===========================================================================
struct CtxSmem {
    float QtF[64][132];                                        // 33,792 B
    union {
        struct { __half XsH[64][40]; __half WH[32][136]; } p1; // 13,824 B
        struct { __half QtH[64][136]; __half kvH[32][136]; } p2; // 26,112 B
    } u;
    float ksum[128];
    float den[64];
};
#define CTX_SMEM_BYTES ((int)sizeof(CtxSmem))

__global__ void __launch_bounds__(256) fused_ctx_kernel(const float* __restrict__ x,
                                                        const float* __restrict__ Wq) {
    extern __shared__ __align__(16) char ctx_smem_raw[];
    CtxSmem& sm = *reinterpret_cast<CtxSmem*>(ctx_smem_raw);

    const int stile = blockIdx.x;
    const int bh    = blockIdx.y;
    const int b = bh / H_, h = bh % H_;

    const float* Wqh = Wq + (size_t)h * D_ * D_;
    const float* Xb  = x + (size_t)b * S_ * E_ + (size_t)h * D_;
    const __half* kv = g_kvh + (size_t)bh * D_ * D_;

    const int tid  = threadIdx.x;
    const int warp = tid >> 5;
    const int wm = warp & 3;     // 16-row blocks (4 x 16 = 64)
    const int wn = warp >> 2;    // 64-col blocks (2 x 64 = 128)
    const int s0 = stile * 64;

    if (tid < 128) sm.ksum[tid] = g_ks[(size_t)bh * D_ + tid];

    // ---- phase 1 (fp16): Qt = phi(X @ Wq) -> QtF ----
    CFragH acc[4];
#pragma unroll
    for (int j = 0; j < 4; j++) wmma::fill_fragment(acc[j], 0.f);

    for (int k0 = 0; k0 < D_; k0 += 32) {
#pragma unroll
        for (int t = 0; t < 2; t++) {       // X: 64x32
            int f4i = tid + t * 256;
            int r = f4i >> 3, c4 = (f4i & 7) * 4;
            f4_to_h4(&sm.u.p1.XsH[r][c4], *(const float4*)&Xb[(size_t)(s0 + r) * E_ + k0 + c4]);
        }
#pragma unroll
        for (int t = 0; t < 4; t++) {       // Wq: 32x128
            int f4i = tid + t * 256;
            int r = f4i >> 5, c4 = (f4i & 31) * 4;
            f4_to_h4(&sm.u.p1.WH[r][c4], *(const float4*)&Wqh[(size_t)(k0 + r) * D_ + c4]);
        }
        __syncthreads();
#pragma unroll
        for (int kk = 0; kk < 2; kk++) {
            AFragH a;
            wmma::load_matrix_sync(a, &sm.u.p1.XsH[wm * 16][kk * 16], 40);
#pragma unroll
            for (int j = 0; j < 4; j++) {
                BFragH bfr;
                wmma::load_matrix_sync(bfr, &sm.u.p1.WH[kk * 16][wn * 64 + j * 16], 136);
                wmma::mma_sync(acc[j], a, bfr, acc[j]);
            }
        }
        __syncthreads();
    }
#pragma unroll
    for (int j = 0; j < 4; j++) {
#pragma unroll
        for (int e = 0; e < acc[j].num_elements; e++) acc[j].x[e] = phi_(acc[j].x[e]);
        wmma::store_matrix_sync(&sm.QtF[wm * 16][wn * 64 + j * 16], acc[j], 132, wmma::mem_row_major);
    }
    __syncthreads();

    // ---- den (64 rows), then scaled convert QtF -> QtH (p1 now dead) ----
    if (tid < 64) {
        float dsum = 0.f;
#pragma unroll
        for (int c = 0; c < 128; c++) dsum = fmaf(sm.QtF[tid][c], sm.ksum[c], dsum);
        sm.den[tid] = DEN_SCALE_ / (dsum + EPS_);
    }
    __syncthreads();
#pragma unroll
    for (int t = 0; t < 16; t++) {
        int i = tid + t * 256;              // 64 rows x 64 half2
        int r = i >> 6, c2 = i & 63;
        float sc = sm.den[r];
        *(__half2*)&sm.u.p2.QtH[r][c2 * 2] =
            __floats2half2_rn(sm.QtF[r][c2 * 2] * sc, sm.QtF[r][c2 * 2 + 1] * sc);
    }
    __syncthreads();

    // ---- phase 2 (fp16): ctx = QtH @ kv ----
#pragma unroll
    for (int j = 0; j < 4; j++) wmma::fill_fragment(acc[j], 0.f);

    for (int k0 = 0; k0 < D_; k0 += 32) {
#pragma unroll
        for (int t = 0; t < 4; t++) {       // kv chunk 32x128 half
            int f = tid + t * 256;
            int r = f >> 5, c4 = (f & 31) * 4;
            *(uint2*)&sm.u.p2.kvH[r][c4] = *(const uint2*)&kv[(size_t)(k0 + r) * D_ + c4];
        }
        __syncthreads();
#pragma unroll
        for (int kk = 0; kk < 2; kk++) {
            AFragH a;
            wmma::load_matrix_sync(a, &sm.u.p2.QtH[wm * 16][k0 + kk * 16], 136);
#pragma unroll
            for (int j = 0; j < 4; j++) {
                BFragH bfr;
                wmma::load_matrix_sync(bfr, &sm.u.p2.kvH[kk * 16][wn * 64 + j * 16], 136);
                wmma::mma_sync(acc[j], a, bfr, acc[j]);
            }
        }
        __syncthreads();
    }

    // ---- epilogue: stage ctx in QtF, write fp16 g_combh (undo 4096 scale) ----
#pragma unroll
    for (int j = 0; j < 4; j++)
        wmma::store_matrix_sync(&sm.QtF[wm * 16][wn * 64 + j * 16], acc[j], 132, wmma::mem_row_major);
    __syncthreads();
#pragma unroll
    for (int t = 0; t < 16; t++) {
        int i = tid + t * 256;
        int r = i >> 6, c2 = i & 63;
        __half2 v = __floats2half2_rn(sm.QtF[r][c2 * 2] * INV_DEN_SCALE_,
                                      sm.QtF[r][c2 * 2 + 1] * INV_DEN_SCALE_);
        *(__half2*)&g_combh[((size_t)(b * S_ + s0 + r)) * E_ + h * D_ + c2 * 2] = v;
    }
}

// ===========================================================================
// Kernel C v2: out = g_combh @ g_woh + bo (fp16 wmma), 128x128 tile, 2-stage
// cp.async, k-step 64 (halved iteration/barrier count). Dynamic smem ~80 KB,
// still 2 CTAs/SM.
// ===========================================================================
#define OKH_TK 64
#define OKH_NIT (E_ / OKH_TK)   // 32

struct OutSmem {
    __half Ah[2][128][72];    // 36,864 B
    __half Bh[2][OKH_TK][136];// 34,816 B
    float  BiasS[16][132];    //  8,448 B
};
#define OUT_SMEM_BYTES ((int)sizeof(OutSmem))

__global__ void __launch_bounds__(256) out_kernel(const float* __restrict__ bo,
                                                  float* __restrict__ out) {
    extern __shared__ __align__(16) char out_smem_raw[];
    OutSmem& sm = *reinterpret_cast<OutSmem*>(out_smem_raw);

    const int col0 = blockIdx.x * 128;
    const int row0 = blockIdx.y * 128;
    const int tid  = threadIdx.x;
    const int warp = tid >> 5;
    const int wm = warp & 3;    // rows wm*32
    const int wn = warp >> 2;   // cols wn*64

    // A tile 128x64 half = 1024 x 16B chunks (8/row), 4 per thread
    const int ar = tid >> 3, ac = (tid & 7) * 8;     // + t*32 rows
    // B tile 64x128 half = 1024 chunks (16/row), 4 per thread
    const int br = tid >> 4, bc = (tid & 15) * 8;    // + t*16 rows

    const __half* Ag = g_combh + (size_t)row0 * E_;
    const __half* Bg = g_woh + (size_t)col0;

#pragma unroll
    for (int t = 0; t < 8; t++) {
        int i = tid + t * 256;
        int r = i >> 7, c = i & 127;
        sm.BiasS[r][c] = bo[col0 + c];
    }
    __syncthreads();

    CFragH acc[2][4];
#pragma unroll
    for (int i = 0; i < 2; i++)
#pragma unroll
        for (int j = 0; j < 4; j++)
            wmma::load_matrix_sync(acc[i][j], &sm.BiasS[0][wn * 64 + j * 16], 132, wmma::mem_row_major);
    __syncthreads();

    // preload stage 0
#pragma unroll
    for (int t = 0; t < 4; t++) {
        cpasync16(&sm.Ah[0][ar + t * 32][ac], &Ag[(size_t)(ar + t * 32) * E_ + ac]);
        cpasync16(&sm.Bh[0][br + t * 16][bc], &Bg[(size_t)(br + t * 16) * E_ + bc]);
    }
    CP_COMMIT();

    for (int it = 0; it < OKH_NIT; it++) {
        const int cur = it & 1;
        if (it + 1 < OKH_NIT) {
            const int nxt = cur ^ 1;
            const int k0 = (it + 1) * OKH_TK;
#pragma unroll
            for (int t = 0; t < 4; t++) {
                cpasync16(&sm.Ah[nxt][ar + t * 32][ac], &Ag[(size_t)(ar + t * 32) * E_ + k0 + ac]);
                cpasync16(&sm.Bh[nxt][br + t * 16][bc], &Bg[(size_t)(k0 + br + t * 16) * E_ + bc]);
            }
        }
        CP_COMMIT();
        CP_WAIT(1);
        __syncthreads();

#pragma unroll
        for (int kk = 0; kk < OKH_TK / 16; kk++) {
            AFragH a[2];
#pragma unroll
            for (int i = 0; i < 2; i++)
                wmma::load_matrix_sync(a[i], &sm.Ah[cur][wm * 32 + i * 16][kk * 16], 72);
#pragma unroll
            for (int j = 0; j < 4; j++) {
                BFragH bfr;
                wmma::load_matrix_sync(bfr, &sm.Bh[cur][kk * 16][wn * 64 + j * 16], 136);
#pragma unroll
                for (int i = 0; i < 2; i++) wmma::mma_sync(acc[i][j], a[i], bfr, acc[i][j]);
            }
        }
        __syncthreads();
    }

#pragma unroll
    for (int i = 0; i < 2; i++)
#pragma unroll
        for (int j = 0; j < 4; j++)
            wmma::store_matrix_sync(out + (size_t)(row0 + wm * 32 + i * 16) * E_ + col0 + wn * 64 + j * 16,
                                    acc[i][j], E_, wmma::mem_row_major);
}

// ===========================================================================
extern "C" void kernel_launch(void* const* d_in, const int* in_sizes, int n_in,
                              void* d_out, int out_size) {
    const float* x  = (const float*)d_in[0];
    const float* Wq = (const float*)d_in[1];
    const float* Wk = (const float*)d_in[2];
    const float* Wv = (const float*)d_in[3];
    const float* Wo = (const float*)d_in[4];
    const float* bo = (const float*)d_in[5];
    float* out = (float*)d_out;

    (void)cudaFuncSetAttribute(fused_ctx_kernel, cudaFuncAttributeMaxDynamicSharedMemorySize, CTX_SMEM_BYTES);
    (void)cudaFuncSetAttribute(out_kernel, cudaFuncAttributeMaxDynamicSharedMemorySize, OUT_SMEM_BYTES);

    wo_half_kernel<<<1024, 256>>>((const float4*)Wo);
    fused_kv_kernel<<<dim3(NCHUNK_, BH_), 256>>>(x, Wk, Wv);
    reduce_kernel<<<BH_, 256>>>();
    fused_ctx_kernel<<<dim3(S_ / 64, BH_), 256, CTX_SMEM_BYTES>>>(x, Wq);
    out_kernel<<<dim3(E_ / 128, (B_ * S_) / 128), 256, OUT_SMEM_BYTES>>>(bo, out);
}

// round 16
// speedup vs baseline: 1.0243x; 1.0243x over previous
#include <cuda_runtime.h>
#include <mma.h>
#include <cuda_fp16.h>
#include <cstdint>

using namespace nvcuda;

#define B_  8
#define S_  2048
#define E_  2048
#define H_  16
#define D_  128
#define BH_ (B_ * H_)
#define NCHUNK_ 4
#define CHUNK_S_ (S_ / NCHUNK_)   // 512
#define EPS_ 1e-6f
#define DEN_SCALE_ 4096.0f
#define INV_DEN_SCALE_ (1.0f / 4096.0f)

typedef wmma::fragment<wmma::matrix_a, 16, 16, 16, __half, wmma::row_major> AFragH;
typedef wmma::fragment<wmma::matrix_a, 16, 16, 16, __half, wmma::col_major> ATFragH;
typedef wmma::fragment<wmma::matrix_b, 16, 16, 16, __half, wmma::row_major> BFragH;
typedef wmma::fragment<wmma::accumulator, 16, 16, 16, float> CFragH;

__device__ __forceinline__ float phi_(float y) { return (y > 0.f) ? (y + 1.f) : expf(y); }

__device__ __forceinline__ void f4_to_h4(__half* smem, const float4 v) {
    __half2 h0 = __floats2half2_rn(v.x, v.y);
    __half2 h1 = __floats2half2_rn(v.z, v.w);
    uint2 u;
    u.x = *(uint32_t*)&h0;
    u.y = *(uint32_t*)&h1;
    *(uint2*)smem = u;
}

__device__ __forceinline__ void cpasync16(void* smem, const void* gmem) {
    uint32_t s = (uint32_t)__cvta_generic_to_shared(smem);
    asm volatile("cp.async.cg.shared.global [%0], [%1], 16;" :: "r"(s), "l"(gmem));
}
#define CP_COMMIT()  asm volatile("cp.async.commit_group;")
#define CP_WAIT(N)   asm volatile("cp.async.wait_group %0;" :: "n"(N))

// ---------------- scratch (__device__ globals; no allocation allowed) ----------------
__device__ float  g_kvp[(size_t)BH_ * NCHUNK_ * D_ * D_];   // 32 MB
__device__ float  g_ksp[(size_t)BH_ * NCHUNK_ * D_];
__device__ __half g_kvh[(size_t)BH_ * D_ * D_];             // 4 MB fp16 kv
__device__ float  g_ks [(size_t)BH_ * D_];
__device__ __half g_combh[(size_t)B_ * S_ * E_];            // 64 MB fp16 combined heads
__device__ __half g_woh [(size_t)E_ * E_];                  // 8 MB fp16 Wo

// ===========================================================================
// Prep: convert Wo -> fp16. (unchanged)
// ===========================================================================
__global__ void wo_half_kernel(const float4* __restrict__ src) {
    const int n4 = (E_ * E_) / 4;
    int i = blockIdx.x * blockDim.x + threadIdx.x;
    int stride = gridDim.x * blockDim.x;
    for (; i < n4; i += stride) {
        float4 v = src[i];
        __half2* d = (__half2*)&g_woh[(size_t)i * 4];
        d[0] = __floats2half2_rn(v.x, v.y);
        d[1] = __floats2half2_rn(v.z, v.w);
    }
}

// ===========================================================================
// Kernel A v3: fused K/V proj + phi + partial kv + ksum, W-RESIDENT.
// Wk/Wv loaded to smem ONCE per block; X tiles streamed. 3 syncs/sub-tile.
// grid = (NCHUNK, BH), block 256. Dynamic smem ~129.5 KB (1 CTA/SM).
// ===========================================================================
struct KvSmem3 {
    __half WkH[128][136];       // 34,816 B  (resident)
    __half WvH[128][136];       // 34,816 B  (resident)
    __half XsH[32][136];        //  8,704 B
    float  StageF[2][32][132];  // 33,792 B  (K and V staged together)
    __half KtH[32][136];        //  8,704 B
    __half VtH[32][136];        //  8,704 B
};
#define KV_SMEM_BYTES ((int)sizeof(KvSmem3))

__global__ void __launch_bounds__(256) fused_kv_kernel(const float* __restrict__ x,
                                                       const float* __restrict__ Wk,
                                                       const float* __restrict__ Wv) {
    extern __shared__ __align__(16) char kv_raw[];
    KvSmem3& sm = *reinterpret_cast<KvSmem3*>(kv_raw);

    const int chunk = blockIdx.x;
    const int bh    = blockIdx.y;
    const int b = bh / H_, h = bh % H_;

    const float* Wkh = Wk + (size_t)h * D_ * D_;
    const float* Wvh = Wv + (size_t)h * D_ * D_;
    const float* Xb  = x + (size_t)b * S_ * E_ + (size_t)h * D_;

    const int tid  = threadIdx.x;
    const int warp = tid >> 5;
    const int lane = tid & 31;
    const int wm1 = warp & 1;    // phase1: 16-row blocks
    const int wn1 = warp >> 1;   // phase1: 32-col blocks
    const int wm2 = warp & 3;    // phase2: 32-row blocks
    const int wn2 = warp >> 2;   // phase2: 64-col blocks

    // ---- load Wk/Wv fully into smem (once) ----
#pragma unroll
    for (int t = 0; t < 16; t++) {
        int idx = tid + t * 256;
        int r = idx >> 5, c4 = (idx & 31) * 4;
        f4_to_h4(&sm.WkH[r][c4], *(const float4*)&Wkh[(size_t)r * D_ + c4]);
        f4_to_h4(&sm.WvH[r][c4], *(const float4*)&Wvh[(size_t)r * D_ + c4]);
    }
    __syncthreads();

    CFragH acc_kv[2][4];
#pragma unroll
    for (int i = 0; i < 2; i++)
#pragma unroll
        for (int j = 0; j < 4; j++) wmma::fill_fragment(acc_kv[i][j], 0.f);

    float ksum_acc = 0.f;

    for (int sub = 0; sub < CHUNK_S_ / 32; sub++) {
        const int s0 = chunk * CHUNK_S_ + sub * 32;

        // ---- load X tile 32x128 (full k range, one sync) ----
#pragma unroll
        for (int t = 0; t < 4; t++) {
            int idx = tid + t * 256;
            int r = idx >> 5, c4 = (idx & 31) * 4;
            f4_to_h4(&sm.XsH[r][c4], *(const float4*)&Xb[(size_t)(s0 + r) * E_ + c4]);
        }
        __syncthreads();

        // ---- phase 1: K/V projections, no intermediate syncs ----
        CFragH acck[2], accv[2];
#pragma unroll
        for (int j = 0; j < 2; j++) { wmma::fill_fragment(acck[j], 0.f); wmma::fill_fragment(accv[j], 0.f); }
#pragma unroll
        for (int kk = 0; kk < 8; kk++) {
            AFragH a;
            wmma::load_matrix_sync(a, &sm.XsH[wm1 * 16][kk * 16], 136);
#pragma unroll
            for (int j = 0; j < 2; j++) {
                BFragH bfr;
                wmma::load_matrix_sync(bfr, &sm.WkH[kk * 16][wn1 * 32 + j * 16], 136);
                wmma::mma_sync(acck[j], a, bfr, acck[j]);
                wmma::load_matrix_sync(bfr, &sm.WvH[kk * 16][wn1 * 32 + j * 16], 136);
                wmma::mma_sync(accv[j], a, bfr, accv[j]);
            }
        }

        // ---- stage K (with phi) and V together ----
#pragma unroll
        for (int j = 0; j < 2; j++) {
#pragma unroll
            for (int e = 0; e < acck[j].num_elements; e++) acck[j].x[e] = phi_(acck[j].x[e]);
            wmma::store_matrix_sync(&sm.StageF[0][wm1 * 16][wn1 * 32 + j * 16], acck[j], 132, wmma::mem_row_major);
            wmma::store_matrix_sync(&sm.StageF[1][wm1 * 16][wn1 * 32 + j * 16], accv[j], 132, wmma::mem_row_major);
        }
        __syncthreads();

        // ---- ksum + convert both stages to half ----
        if (warp < 4) {
            const int col = warp * 32 + lane;
#pragma unroll 8
            for (int r = 0; r < 32; r++) ksum_acc += sm.StageF[0][r][col];
        }
#pragma unroll
        for (int t = 0; t < 8; t++) {
            int i = tid + t * 256;
            int r = i >> 6, c2 = i & 63;
            *(__half2*)&sm.KtH[r][c2 * 2] =
                __floats2half2_rn(sm.StageF[0][r][c2 * 2], sm.StageF[0][r][c2 * 2 + 1]);
            *(__half2*)&sm.VtH[r][c2 * 2] =
                __floats2half2_rn(sm.StageF[1][r][c2 * 2], sm.StageF[1][r][c2 * 2 + 1]);
        }
        __syncthreads();

        // ---- phase 2: kv += KtH^T @ VtH ----
#pragma unroll
        for (int kk = 0; kk < 2; kk++) {
            ATFragH a2[2];
#pragma unroll
            for (int i = 0; i < 2; i++)
                wmma::load_matrix_sync(a2[i], &sm.KtH[kk * 16][wm2 * 32 + i * 16], 136);
#pragma unroll
            for (int j = 0; j < 4; j++) {
                BFragH bfr;
                wmma::load_matrix_sync(bfr, &sm.VtH[kk * 16][wn2 * 64 + j * 16], 136);
#pragma unroll
                for (int i = 0; i < 2; i++) wmma::mma_sync(acc_kv[i][j], a2[i], bfr, acc_kv[i][j]);
            }
        }
        // next sub's X-load sync guarantees phase-2 readers are done before
        // KtH/VtH/StageF are rewritten (those writes come after further syncs)
    }

    float* kvp = g_kvp + ((size_t)bh * NCHUNK_ + chunk) * D_ * D_;
#pragma unroll
    for (int i = 0; i < 2; i++)
#pragma unroll
        for (int j = 0; j < 4; j++)
            wmma::store_matrix_sync(&kvp[(size_t)(wm2 * 32 + i * 16) * D_ + wn2 * 64 + j * 16],
                                    acc_kv[i][j], D_, wmma::mem_row_major);
    if (warp < 4)
        g_ksp[((size_t)bh * NCHUNK_ + chunk) * D_ + warp * 32 + lane] = ksum_acc;
}

// ===========================================================================
// Kernel A2: reduce the NCHUNK partials; kv -> fp16. (unchanged)
// ===========================================================================
__global__ void reduce_kernel() {
    const int bh = blockIdx.x;
    const int tid = threadIdx.x;
    const float* kvp = g_kvp + (size_t)bh * NCHUNK_ * D_ * D_;
    __half* kv = g_kvh + (size_t)bh * D_ * D_;
    for (int i = tid; i < D_ * D_; i += 256) {
        float s = 0.f;
#pragma unroll
        for (int c = 0; c < NCHUNK_; c++) s += kvp[(size_t)c * D_ * D_ + i];
        kv[i] = __float2half_rn(s);
    }
    if (tid < D_) {
        const float* ksp = g_ksp + (size_t)bh * NCHUNK_ * D_;
        float s = 0.f;
#pragma unroll
        for (int c = 0; c < NCHUNK_; c++) s += ksp[(size_t)c * D_ + tid];
        g_ks[(size_t)bh * D_ + tid] = s;
    }
}

// ===========================================================================
// Kernel B v3: fused Q-proj + phi + ctx, Wq & kv RESIDENT. 64-row blocks,
// 6 syncs per block total. grid = (S/64, BH), block 256.
// Dynamic smem ~121 KB (1 CTA/SM).
// ===========================================================================
struct CtxSmem3 {
    __half WqH[128][136];                                   // 34,816 B (resident)
    __half kvH[128][136];                                   // 34,816 B (resident)
    union { __half XsH[64][136]; __half QtH[64][136]; } u;  // 17,408 B
    float QtF[64][132];                                     // 33,792 B
    float ksum[128];
    float den[64];
};
#define CTX_SMEM_BYTES ((int)sizeof(CtxSmem3))

__global__ void __launch_bounds__(256) fused_ctx_kernel(const float* __restrict__ x,
                                                        const float* __restrict__ Wq) {
    extern __shared__ __align__(16) char ctx_raw[];
    CtxSmem3& sm = *reinterpret_cast<CtxSmem3*>(ctx_raw);

    const int stile = blockIdx.x;
    const int bh    = blockIdx.y;
    const int b = bh / H_, h = bh % H_;

    const float* Wqh = Wq + (size_t)h * D_ * D_;
    const float* Xb  = x + (size_t)b * S_ * E_ + (size_t)h * D_;
    const __half* kv = g_kvh + (size_t)bh * D_ * D_;

    const int tid  = threadIdx.x;
    const int warp = tid >> 5;
    const int wm = warp & 3;     // 16-row blocks
    const int wn = warp >> 2;    // 64-col blocks
    const int s0 = stile * 64;

    // ---- load Wq (convert) and kv (copy) fully into smem, once ----
#pragma unroll
    for (int t = 0; t < 16; t++) {
        int idx = tid + t * 256;
        int r = idx >> 5, c4 = (idx & 31) * 4;
        f4_to_h4(&sm.WqH[r][c4], *(const float4*)&Wqh[(size_t)r * D_ + c4]);
        *(uint2*)&sm.kvH[r][c4] = *(const uint2*)&kv[(size_t)r * D_ + c4];
    }
    if (tid < 128) sm.ksum[tid] = g_ks[(size_t)bh * D_ + tid];
    __syncthreads();

    // ---- load X tile 64x128 (one sync) ----
#pragma unroll
    for (int t = 0; t < 8; t++) {
        int idx = tid + t * 256;
        int r = idx >> 5, c4 = (idx & 31) * 4;
        f4_to_h4(&sm.u.XsH[r][c4], *(const float4*)&Xb[(size_t)(s0 + r) * E_ + c4]);
    }
    __syncthreads();

    // ---- phase 1: Qt = phi(X @ Wq), no intermediate syncs ----
    CFragH acc[4];
#pragma unroll
    for (int j = 0; j < 4; j++) wmma::fill_fragment(acc[j], 0.f);
#pragma unroll
    for (int kk = 0; kk < 8; kk++) {
        AFragH a;
        wmma::load_matrix_sync(a, &sm.u.XsH[wm * 16][kk * 16], 136);
#pragma unroll
        for (int j = 0; j < 4; j++) {
            BFragH bfr;
            wmma::load_matrix_sync(bfr, &sm.WqH[kk * 16][wn * 64 + j * 16], 136);
            wmma::mma_sync(acc[j], a, bfr, acc[j]);
        }
    }
#pragma unroll
    for (int j = 0; j < 4; j++) {
#pragma unroll
        for (int e = 0; e < acc[j].num_elements; e++) acc[j].x[e] = phi_(acc[j].x[e]);
        wmma::store_matrix_sync(&sm.QtF[wm * 16][wn * 64 + j * 16], acc[j], 132, wmma::mem_row_major);
    }
    __syncthreads();

    // ---- den, then scaled convert QtF -> QtH (overwrites XsH, now dead) ----
    if (tid < 64) {
        float dsum = 0.f;
#pragma unroll
        for (int c = 0; c < 128; c++) dsum = fmaf(sm.QtF[tid][c], sm.ksum[c], dsum);
        sm.den[tid] = DEN_SCALE_ / (dsum + EPS_);
    }
    __syncthreads();
#pragma unroll
    for (int t = 0; t < 16; t++) {
        int i = tid + t * 256;
        int r = i >> 6, c2 = i & 63;
        float sc = sm.den[r];
        *(__half2*)&sm.u.QtH[r][c2 * 2] =
            __floats2half2_rn(sm.QtF[r][c2 * 2] * sc, sm.QtF[r][c2 * 2 + 1] * sc);
    }
    __syncthreads();

    // ---- phase 2: ctx = QtH @ kvH, no intermediate syncs ----
#pragma unroll
    for (int j = 0; j < 4; j++) wmma::fill_fragment(acc[j], 0.f);
#pragma unroll
    for (int kk = 0; kk < 8; kk++) {
        AFragH a;
        wmma::load_matrix_sync(a, &sm.u.QtH[wm * 16][kk * 16], 136);
#pragma unroll
        for (int j = 0; j < 4; j++) {
            BFragH bfr;
            wmma::load_matrix_sync(bfr, &sm.kvH[kk * 16][wn * 64 + j * 16], 136);
            wmma::mma_sync(acc[j], a, bfr, acc[j]);
        }
    }
#pragma unroll
    for (int j = 0; j < 4; j++)
        wmma::store_matrix_sync(&sm.QtF[wm * 16][wn * 64 + j * 16], acc[j], 132, wmma::mem_row_major);
    __syncthreads();

    // ---- epilogue: fp16 write to g_combh (undo 4096 scale) ----
#pragma unroll
    for (int t = 0; t < 16; t++) {
        int i = tid + t * 256;
        int r = i >> 6, c2 = i & 63;
        __half2 v = __floats2half2_rn(sm.QtF[r][c2 * 2] * INV_DEN_SCALE_,
                                      sm.QtF[r][c2 * 2 + 1] * INV_DEN_SCALE_);
        *(__half2*)&g_combh[((size_t)(b * S_ + s0 + r)) * E_ + h * D_ + c2 * 2] = v;
    }
}

// ===========================================================================
// Kernel C: out = g_combh @ g_woh + bo — EXACT round-13 version
// (k-step 32, static smem, 2 CTAs/SM). Frozen local optimum.
// ===========================================================================
#define OKH_TK 32
#define OKH_NIT (E_ / OKH_TK)   // 64

__global__ void __launch_bounds__(256, 2) out_kernel(const float* __restrict__ bo,
                                                     float* __restrict__ out) {
    __shared__ __align__(16) __half Ah[2][128][40];
    __shared__ __align__(16) __half Bh[2][OKH_TK][136];
    __shared__ __align__(16) float BiasS[16][132];

    const int col0 = blockIdx.x * 128;
    const int row0 = blockIdx.y * 128;
    const int tid  = threadIdx.x;
    const int warp = tid >> 5;
    const int wm = warp & 3;
    const int wn = warp >> 2;

    const int ar0 = tid >> 2,         ac0 = (tid & 3) * 8;
    const int ar1 = (tid + 256) >> 2, ac1 = ac0;
    const int br0 = tid >> 4,         bc0 = (tid & 15) * 8;
    const int br1 = (tid + 256) >> 4, bc1 = bc0;

    const __half* Ag = g_combh + (size_t)row0 * E_;
    const __half* Bg = g_woh + (size_t)col0;

#pragma unroll
    for (int t = 0; t < 8; t++) {
        int i = tid + t * 256;
        int r = i >> 7, c = i & 127;
        BiasS[r][c] = bo[col0 + c];
    }
    __syncthreads();

    CFragH acc[2][4];
#pragma unroll
    for (int i = 0; i < 2; i++)
#pragma unroll
        for (int j = 0; j < 4; j++)
            wmma::load_matrix_sync(acc[i][j], &BiasS[0][wn * 64 + j * 16], 132, wmma::mem_row_major);
    __syncthreads();

    {
        cpasync16(&Ah[0][ar0][ac0], &Ag[(size_t)ar0 * E_ + ac0]);
        cpasync16(&Ah[0][ar1][ac1], &Ag[(size_t)ar1 * E_ + ac1]);
        cpasync16(&Bh[0][br0][bc0], &Bg[(size_t)br0 * E_ + bc0]);
        cpasync16(&Bh[0][br1][bc1], &Bg[(size_t)br1 * E_ + bc1]);
    }
    CP_COMMIT();

    for (int it = 0; it < OKH_NIT; it++) {
        const int cur = it & 1;
        if (it + 1 < OKH_NIT) {
            const int nxt = cur ^ 1;
            const int k0 = (it + 1) * OKH_TK;
            cpasync16(&Ah[nxt][ar0][ac0], &Ag[(size_t)ar0 * E_ + k0 + ac0]);
            cpasync16(&Ah[nxt][ar1][ac1], &Ag[(size_t)ar1 * E_ + k0 + ac1]);
            cpasync16(&Bh[nxt][br0][bc0], &Bg[(size_t)(k0 + br0) * E_ + bc0]);
            cpasync16(&Bh[nxt][br1][bc1], &Bg[(size_t)(k0 + br1) * E_ + bc1]);
        }
        CP_COMMIT();
        CP_WAIT(1);
        __syncthreads();

#pragma unroll
        for (int kk = 0; kk < OKH_TK / 16; kk++) {
            AFragH a[2];
#pragma unroll
            for (int i = 0; i < 2; i++)
                wmma::load_matrix_sync(a[i], &Ah[cur][wm * 32 + i * 16][kk * 16], 40);
#pragma unroll
            for (int j = 0; j < 4; j++) {
                BFragH bfr;
                wmma::load_matrix_sync(bfr, &Bh[cur][kk * 16][wn * 64 + j * 16], 136);
#pragma unroll
                for (int i = 0; i < 2; i++) wmma::mma_sync(acc[i][j], a[i], bfr, acc[i][j]);
            }
        }
        __syncthreads();
    }

#pragma unroll
    for (int i = 0; i < 2; i++)
#pragma unroll
        for (int j = 0; j < 4; j++)
            wmma::store_matrix_sync(out + (size_t)(row0 + wm * 32 + i * 16) * E_ + col0 + wn * 64 + j * 16,
                                    acc[i][j], E_, wmma::mem_row_major);
}

// ===========================================================================
extern "C" void kernel_launch(void* const* d_in, const int* in_sizes, int n_in,
                              void* d_out, int out_size) {
    const float* x  = (const float*)d_in[0];
    const float* Wq = (const float*)d_in[1];
    const float* Wk = (const float*)d_in[2];
    const float* Wv = (const float*)d_in[3];
    const float* Wo = (const float*)d_in[4];
    const float* bo = (const float*)d_in[5];
    float* out = (float*)d_out;

    (void)cudaFuncSetAttribute(fused_kv_kernel, cudaFuncAttributeMaxDynamicSharedMemorySize, KV_SMEM_BYTES);
    (void)cudaFuncSetAttribute(fused_ctx_kernel, cudaFuncAttributeMaxDynamicSharedMemorySize, CTX_SMEM_BYTES);

    wo_half_kernel<<<1024, 256>>>((const float4*)Wo);
    fused_kv_kernel<<<dim3(NCHUNK_, BH_), 256, KV_SMEM_BYTES>>>(x, Wk, Wv);
    reduce_kernel<<<BH_, 256>>>();
    fused_ctx_kernel<<<dim3(S_ / 64, BH_), 256, CTX_SMEM_BYTES>>>(x, Wq);
    out_kernel<<<dim3(E_ / 128, (B_ * S_) / 128), 256>>>(bo, out);
}

// round 17
// speedup vs baseline: 1.0455x; 1.0208x over previous
#include <cuda_runtime.h>
#include <mma.h>
#include <cuda_fp16.h>
#include <cstdint>

using namespace nvcuda;

#define B_  8
#define S_  2048
#define E_  2048
#define H_  16
#define D_  128
#define BH_ (B_ * H_)
#define NCHUNK_ 4
#define CHUNK_S_ (S_ / NCHUNK_)   // 512
#define EPS_ 1e-6f
#define DEN_SCALE_ 4096.0f
#define INV_DEN_SCALE_ (1.0f / 4096.0f)

typedef wmma::fragment<wmma::matrix_a, 16, 16, 16, __half, wmma::row_major> AFragH;
typedef wmma::fragment<wmma::matrix_a, 16, 16, 16, __half, wmma::col_major> ATFragH;
typedef wmma::fragment<wmma::matrix_b, 16, 16, 16, __half, wmma::row_major> BFragH;
typedef wmma::fragment<wmma::accumulator, 16, 16, 16, float> CFragH;

__device__ __forceinline__ float phi_(float y) { return (y > 0.f) ? (y + 1.f) : expf(y); }

__device__ __forceinline__ void f4_to_h4(__half* smem, const float4 v) {
    __half2 h0 = __floats2half2_rn(v.x, v.y);
    __half2 h1 = __floats2half2_rn(v.z, v.w);
    uint2 u;
    u.x = *(uint32_t*)&h0;
    u.y = *(uint32_t*)&h1;
    *(uint2*)smem = u;
}

__device__ __forceinline__ void cpasync16(void* smem, const void* gmem) {
    uint32_t s = (uint32_t)__cvta_generic_to_shared(smem);
    asm volatile("cp.async.cg.shared.global [%0], [%1], 16;" :: "r"(s), "l"(gmem));
}
#define CP_COMMIT()  asm volatile("cp.async.commit_group;")
#define CP_WAIT(N)   asm volatile("cp.async.wait_group %0;" :: "n"(N))

// ---------------- scratch (__device__ globals; no allocation allowed) ----------------
__device__ float  g_kvp[(size_t)BH_ * NCHUNK_ * D_ * D_];   // 32 MB
__device__ float  g_ksp[(size_t)BH_ * NCHUNK_ * D_];
__device__ __half g_kvh[(size_t)BH_ * D_ * D_];             // 4 MB fp16 kv
__device__ float  g_ks [(size_t)BH_ * D_];
__device__ __half g_combh[(size_t)B_ * S_ * E_];            // 64 MB fp16 combined heads
__device__ __half g_woh [(size_t)E_ * E_];                  // 8 MB fp16 Wo

// ===========================================================================
// Prep: convert Wo -> fp16. (unchanged)
// ===========================================================================
__global__ void wo_half_kernel(const float4* __restrict__ src) {
    const int n4 = (E_ * E_) / 4;
    int i = blockIdx.x * blockDim.x + threadIdx.x;
    int stride = gridDim.x * blockDim.x;
    for (; i < n4; i += stride) {
        float4 v = src[i];
        __half2* d = (__half2*)&g_woh[(size_t)i * 4];
        d[0] = __floats2half2_rn(v.x, v.y);
        d[1] = __floats2half2_rn(v.z, v.w);
    }
}

// ===========================================================================
// Kernel A v3: fused K/V proj + phi + partial kv + ksum, W-RESIDENT.
// (unchanged from passing round 16 — the winner there)
// ===========================================================================
struct KvSmem3 {
    __half WkH[128][136];
    __half WvH[128][136];
    __half XsH[32][136];
    float  StageF[2][32][132];
    __half KtH[32][136];
    __half VtH[32][136];
};
#define KV_SMEM_BYTES ((int)sizeof(KvSmem3))

__global__ void __launch_bounds__(256) fused_kv_kernel(const float* __restrict__ x,
                                                       const float* __restrict__ Wk,
                                                       const float* __restrict__ Wv) {
    extern __shared__ __align__(16) char kv_raw[];
    KvSmem3& sm = *reinterpret_cast<KvSmem3*>(kv_raw);

    const int chunk = blockIdx.x;
    const int bh    = blockIdx.y;
    const int b = bh / H_, h = bh % H_;

    const float* Wkh = Wk + (size_t)h * D_ * D_;
    const float* Wvh = Wv + (size_t)h * D_ * D_;
    const float* Xb  = x + (size_t)b * S_ * E_ + (size_t)h * D_;

    const int tid  = threadIdx.x;
    const int warp = tid >> 5;
    const int lane = tid & 31;
    const int wm1 = warp & 1;
    const int wn1 = warp >> 1;
    const int wm2 = warp & 3;
    const int wn2 = warp >> 2;

#pragma unroll
    for (int t = 0; t < 16; t++) {
        int idx = tid + t * 256;
        int r = idx >> 5, c4 = (idx & 31) * 4;
        f4_to_h4(&sm.WkH[r][c4], *(const float4*)&Wkh[(size_t)r * D_ + c4]);
        f4_to_h4(&sm.WvH[r][c4], *(const float4*)&Wvh[(size_t)r * D_ + c4]);
    }
    __syncthreads();

    CFragH acc_kv[2][4];
#pragma unroll
    for (int i = 0; i < 2; i++)
#pragma unroll
        for (int j = 0; j < 4; j++) wmma::fill_fragment(acc_kv[i][j], 0.f);

    float ksum_acc = 0.f;

    for (int sub = 0; sub < CHUNK_S_ / 32; sub++) {
        const int s0 = chunk * CHUNK_S_ + sub * 32;

#pragma unroll
        for (int t = 0; t < 4; t++) {
            int idx = tid + t * 256;
            int r = idx >> 5, c4 = (idx & 31) * 4;
            f4_to_h4(&sm.XsH[r][c4], *(const float4*)&Xb[(size_t)(s0 + r) * E_ + c4]);
        }
        __syncthreads();

        CFragH acck[2], accv[2];
#pragma unroll
        for (int j = 0; j < 2; j++) { wmma::fill_fragment(acck[j], 0.f); wmma::fill_fragment(accv[j], 0.f); }
#pragma unroll
        for (int kk = 0; kk < 8; kk++) {
            AFragH a;
            wmma::load_matrix_sync(a, &sm.XsH[wm1 * 16][kk * 16], 136);
#pragma unroll
            for (int j = 0; j < 2; j++) {
                BFragH bfr;
                wmma::load_matrix_sync(bfr, &sm.WkH[kk * 16][wn1 * 32 + j * 16], 136);
                wmma::mma_sync(acck[j], a, bfr, acck[j]);
                wmma::load_matrix_sync(bfr, &sm.WvH[kk * 16][wn1 * 32 + j * 16], 136);
                wmma::mma_sync(accv[j], a, bfr, accv[j]);
            }
        }

#pragma unroll
        for (int j = 0; j < 2; j++) {
#pragma unroll
            for (int e = 0; e < acck[j].num_elements; e++) acck[j].x[e] = phi_(acck[j].x[e]);
            wmma::store_matrix_sync(&sm.StageF[0][wm1 * 16][wn1 * 32 + j * 16], acck[j], 132, wmma::mem_row_major);
            wmma::store_matrix_sync(&sm.StageF[1][wm1 * 16][wn1 * 32 + j * 16], accv[j], 132, wmma::mem_row_major);
        }
        __syncthreads();

        if (warp < 4) {
            const int col = warp * 32 + lane;
#pragma unroll 8
            for (int r = 0; r < 32; r++) ksum_acc += sm.StageF[0][r][col];
        }
#pragma unroll
        for (int t = 0; t < 8; t++) {
            int i = tid + t * 256;
            int r = i >> 6, c2 = i & 63;
            *(__half2*)&sm.KtH[r][c2 * 2] =
                __floats2half2_rn(sm.StageF[0][r][c2 * 2], sm.StageF[0][r][c2 * 2 + 1]);
            *(__half2*)&sm.VtH[r][c2 * 2] =
                __floats2half2_rn(sm.StageF[1][r][c2 * 2], sm.StageF[1][r][c2 * 2 + 1]);
        }
        __syncthreads();

#pragma unroll
        for (int kk = 0; kk < 2; kk++) {
            ATFragH a2[2];
#pragma unroll
            for (int i = 0; i < 2; i++)
                wmma::load_matrix_sync(a2[i], &sm.KtH[kk * 16][wm2 * 32 + i * 16], 136);
#pragma unroll
            for (int j = 0; j < 4; j++) {
                BFragH bfr;
                wmma::load_matrix_sync(bfr, &sm.VtH[kk * 16][wn2 * 64 + j * 16], 136);
#pragma unroll
                for (int i = 0; i < 2; i++) wmma::mma_sync(acc_kv[i][j], a2[i], bfr, acc_kv[i][j]);
            }
        }
    }

    float* kvp = g_kvp + ((size_t)bh * NCHUNK_ + chunk) * D_ * D_;
#pragma unroll
    for (int i = 0; i < 2; i++)
#pragma unroll
        for (int j = 0; j < 4; j++)
            wmma::store_matrix_sync(&kvp[(size_t)(wm2 * 32 + i * 16) * D_ + wn2 * 64 + j * 16],
                                    acc_kv[i][j], D_, wmma::mem_row_major);
    if (warp < 4)
        g_ksp[((size_t)bh * NCHUNK_ + chunk) * D_ + warp * 32 + lane] = ksum_acc;
}

// ===========================================================================
// Kernel A2: reduce the NCHUNK partials; kv -> fp16. (unchanged)
// ===========================================================================
__global__ void reduce_kernel() {
    const int bh = blockIdx.x;
    const int tid = threadIdx.x;
    const float* kvp = g_kvp + (size_t)bh * NCHUNK_ * D_ * D_;
    __half* kv = g_kvh + (size_t)bh * D_ * D_;
    for (int i = tid; i < D_ * D_; i += 256) {
        float s = 0.f;
#pragma unroll
        for (int c = 0; c < NCHUNK_; c++) s += kvp[(size_t)c * D_ * D_ + i];
        kv[i] = __float2half_rn(s);
    }
    if (tid < D_) {
        const float* ksp = g_ksp + (size_t)bh * NCHUNK_ * D_;
        float s = 0.f;
#pragma unroll
        for (int c = 0; c < NCHUNK_; c++) s += ksp[(size_t)c * D_ + tid];
        g_ks[(size_t)bh * D_ + tid] = s;
    }
}

// ===========================================================================
// Kernel B: fused Q-proj + phi + ctx — EXACT round-10 version (184 us,
// occ 36%). Static smem, 32-row tiles.
// ===========================================================================
union CtxU {
    struct { __half XsH[32][40]; __half WH[32][136]; } p1;
    struct { __half QtH[32][136]; __half kvH[32][136]; } p2;
};

__global__ void __launch_bounds__(256) fused_ctx_kernel(const float* __restrict__ x,
                                                        const float* __restrict__ Wq) {
    __shared__ float QtF[32][132];
    __shared__ CtxU u;
    __shared__ float ksum_s[128];
    __shared__ float den_s[32];

    const int stile = blockIdx.x;
    const int bh    = blockIdx.y;
    const int b = bh / H_, h = bh % H_;

    const float* Wqh = Wq + (size_t)h * D_ * D_;
    const float* Xb  = x + (size_t)b * S_ * E_ + (size_t)h * D_;
    const __half* kv = g_kvh + (size_t)bh * D_ * D_;

    const int tid  = threadIdx.x;
    const int warp = tid >> 5;
    const int wm = warp & 1;
    const int wn = warp >> 1;
    const int s0 = stile * 32;

    if (tid < 128) ksum_s[tid] = g_ks[(size_t)bh * D_ + tid];

    CFragH acc[2];
#pragma unroll
    for (int j = 0; j < 2; j++) wmma::fill_fragment(acc[j], 0.f);

    for (int k0 = 0; k0 < D_; k0 += 32) {
        {
            int r = tid >> 3, c4 = (tid & 7) * 4;
            f4_to_h4(&u.p1.XsH[r][c4], *(const float4*)&Xb[(size_t)(s0 + r) * E_ + k0 + c4]);
        }
#pragma unroll
        for (int t = 0; t < 4; t++) {
            int f4i = tid + t * 256;
            int r = f4i >> 5, c4 = (f4i & 31) * 4;
            f4_to_h4(&u.p1.WH[r][c4], *(const float4*)&Wqh[(size_t)(k0 + r) * D_ + c4]);
        }
        __syncthreads();
#pragma unroll
        for (int kk = 0; kk < 2; kk++) {
            AFragH a;
            wmma::load_matrix_sync(a, &u.p1.XsH[wm * 16][kk * 16], 40);
#pragma unroll
            for (int j = 0; j < 2; j++) {
                BFragH bfr;
                wmma::load_matrix_sync(bfr, &u.p1.WH[kk * 16][wn * 32 + j * 16], 136);
                wmma::mma_sync(acc[j], a, bfr, acc[j]);
            }
        }
        __syncthreads();
    }
#pragma unroll
    for (int j = 0; j < 2; j++) {
#pragma unroll
        for (int e = 0; e < acc[j].num_elements; e++) acc[j].x[e] = phi_(acc[j].x[e]);
        wmma::store_matrix_sync(&QtF[wm * 16][wn * 32 + j * 16], acc[j], 132, wmma::mem_row_major);
    }
    __syncthreads();

    if (tid < 32) {
        float dsum = 0.f;
#pragma unroll
        for (int c = 0; c < 128; c++) dsum = fmaf(QtF[tid][c], ksum_s[c], dsum);
        den_s[tid] = DEN_SCALE_ / (dsum + EPS_);
    }
    __syncthreads();
#pragma unroll
    for (int t = 0; t < 8; t++) {
        int i = tid + t * 256;
        int r = i >> 6, c2 = i & 63;
        float sc = den_s[r];
        *(__half2*)&u.p2.QtH[r][c2 * 2] =
            __floats2half2_rn(QtF[r][c2 * 2] * sc, QtF[r][c2 * 2 + 1] * sc);
    }
    __syncthreads();

#pragma unroll
    for (int j = 0; j < 2; j++) wmma::fill_fragment(acc[j], 0.f);

    for (int k0 = 0; k0 < D_; k0 += 32) {
#pragma unroll
        for (int t = 0; t < 4; t++) {
            int f = tid + t * 256;
            int r = f >> 5, c4 = (f & 31) * 4;
            *(uint2*)&u.p2.kvH[r][c4] = *(const uint2*)&kv[(size_t)(k0 + r) * D_ + c4];
        }
        __syncthreads();
#pragma unroll
        for (int kk = 0; kk < 2; kk++) {
            AFragH a;
            wmma::load_matrix_sync(a, &u.p2.QtH[wm * 16][k0 + kk * 16], 136);
#pragma unroll
            for (int j = 0; j < 2; j++) {
                BFragH bfr;
                wmma::load_matrix_sync(bfr, &u.p2.kvH[kk * 16][wn * 32 + j * 16], 136);
                wmma::mma_sync(acc[j], a, bfr, acc[j]);
            }
        }
        __syncthreads();
    }

#pragma unroll
    for (int j = 0; j < 2; j++)
        wmma::store_matrix_sync(&QtF[wm * 16][wn * 32 + j * 16], acc[j], 132, wmma::mem_row_major);
    __syncthreads();
#pragma unroll
    for (int t = 0; t < 8; t++) {
        int i = tid + t * 256;
        int r = i >> 6, c2 = i & 63;
        __half2 v = __floats2half2_rn(QtF[r][c2 * 2] * INV_DEN_SCALE_,
                                      QtF[r][c2 * 2 + 1] * INV_DEN_SCALE_);
        *(__half2*)&g_combh[((size_t)(b * S_ + s0 + r)) * E_ + h * D_ + c2 * 2] = v;
    }
}

// ===========================================================================
// Kernel C v4: out = g_combh @ g_woh + bo. 128x128 tile, k-step 32 (frozen
// geometry), but 3-STAGE cp.async with ONE sync/iter, 2 CTAs/SM preserved.
// Dynamic smem 65,280 B (x2 = 130.6 KB/SM).
// ===========================================================================
#define OKH_TK 32
#define OKH_NIT (E_ / OKH_TK)   // 64

struct OutSmem3 {
    __half Ah[3][128][40];    // 30,720 B
    __half Bh[3][OKH_TK][136];// 26,112 B
    float  BiasS[16][132];    //  8,448 B
};
#define OUT_SMEM_BYTES ((int)sizeof(OutSmem3))

__global__ void __launch_bounds__(256, 2) out_kernel(const float* __restrict__ bo,
                                                     float* __restrict__ out) {
    extern __shared__ __align__(16) char out_raw[];
    OutSmem3& sm = *reinterpret_cast<OutSmem3*>(out_raw);

    const int col0 = blockIdx.x * 128;
    const int row0 = blockIdx.y * 128;
    const int tid  = threadIdx.x;
    const int warp = tid >> 5;
    const int wm = warp & 3;
    const int wn = warp >> 2;

    const int ar0 = tid >> 2,         ac0 = (tid & 3) * 8;
    const int ar1 = (tid + 256) >> 2, ac1 = ac0;
    const int br0 = tid >> 4,         bc0 = (tid & 15) * 8;
    const int br1 = (tid + 256) >> 4, bc1 = bc0;

    const __half* Ag = g_combh + (size_t)row0 * E_;
    const __half* Bg = g_woh + (size_t)col0;

#pragma unroll
    for (int t = 0; t < 8; t++) {
        int i = tid + t * 256;
        int r = i >> 7, c = i & 127;
        sm.BiasS[r][c] = bo[col0 + c];
    }
    __syncthreads();

    CFragH acc[2][4];
#pragma unroll
    for (int i = 0; i < 2; i++)
#pragma unroll
        for (int j = 0; j < 4; j++)
            wmma::load_matrix_sync(acc[i][j], &sm.BiasS[0][wn * 64 + j * 16], 132, wmma::mem_row_major);
    __syncthreads();

    // prologue: stages 0 and 1
#pragma unroll
    for (int s = 0; s < 2; s++) {
        const int k0 = s * OKH_TK;
        cpasync16(&sm.Ah[s][ar0][ac0], &Ag[(size_t)ar0 * E_ + k0 + ac0]);
        cpasync16(&sm.Ah[s][ar1][ac1], &Ag[(size_t)ar1 * E_ + k0 + ac1]);
        cpasync16(&sm.Bh[s][br0][bc0], &Bg[(size_t)(k0 + br0) * E_ + bc0]);
        cpasync16(&sm.Bh[s][br1][bc1], &Bg[(size_t)(k0 + br1) * E_ + bc1]);
        CP_COMMIT();
    }

    for (int it = 0; it < OKH_NIT; it++) {
        const int cur = it % 3;
        CP_WAIT(1);          // oldest group (stage cur) complete
        __syncthreads();     // also orders reuse: stage (it+2)%3 == (it-1)%3 readers done

        if (it + 2 < OKH_NIT) {
            const int nxt = (it + 2) % 3;
            const int k0 = (it + 2) * OKH_TK;
            cpasync16(&sm.Ah[nxt][ar0][ac0], &Ag[(size_t)ar0 * E_ + k0 + ac0]);
            cpasync16(&sm.Ah[nxt][ar1][ac1], &Ag[(size_t)ar1 * E_ + k0 + ac1]);
            cpasync16(&sm.Bh[nxt][br0][bc0], &Bg[(size_t)(k0 + br0) * E_ + bc0]);
            cpasync16(&sm.Bh[nxt][br1][bc1], &Bg[(size_t)(k0 + br1) * E_ + bc1]);
        }
        CP_COMMIT();

#pragma unroll
        for (int kk = 0; kk < OKH_TK / 16; kk++) {
            AFragH a[2];
#pragma unroll
            for (int i = 0; i < 2; i++)
                wmma::load_matrix_sync(a[i], &sm.Ah[cur][wm * 32 + i * 16][kk * 16], 40);
#pragma unroll
            for (int j = 0; j < 4; j++) {
                BFragH bfr;
                wmma::load_matrix_sync(bfr, &sm.Bh[cur][kk * 16][wn * 64 + j * 16], 136);
#pragma unroll
                for (int i = 0; i < 2; i++) wmma::mma_sync(acc[i][j], a[i], bfr, acc[i][j]);
            }
        }
    }

#pragma unroll
    for (int i = 0; i < 2; i++)
#pragma unroll
        for (int j = 0; j < 4; j++)
            wmma::store_matrix_sync(out + (size_t)(row0 + wm * 32 + i * 16) * E_ + col0 + wn * 64 + j * 16,
                                    acc[i][j], E_, wmma::mem_row_major);
}

// ===========================================================================
extern "C" void kernel_launch(void* const* d_in, const int* in_sizes, int n_in,
                              void* d_out, int out_size) {
    const float* x  = (const float*)d_in[0];
    const float* Wq = (const float*)d_in[1];
    const float* Wk = (const float*)d_in[2];
    const float* Wv = (const float*)d_in[3];
    const float* Wo = (const float*)d_in[4];
    const float* bo = (const float*)d_in[5];
    float* out = (float*)d_out;

    (void)cudaFuncSetAttribute(fused_kv_kernel, cudaFuncAttributeMaxDynamicSharedMemorySize, KV_SMEM_BYTES);
    (void)cudaFuncSetAttribute(out_kernel, cudaFuncAttributeMaxDynamicSharedMemorySize, OUT_SMEM_BYTES);

    wo_half_kernel<<<1024, 256>>>((const float4*)Wo);
    fused_kv_kernel<<<dim3(NCHUNK_, BH_), 256, KV_SMEM_BYTES>>>(x, Wk, Wv);
    reduce_kernel<<<BH_, 256>>>();
    fused_ctx_kernel<<<dim3(S_ / 32, BH_), 256>>>(x, Wq);
    out_kernel<<<dim3(E_ / 128, (B_ * S_) / 128), 256, OUT_SMEM_BYTES>>>(bo, out);
}